// round 1
// baseline (speedup 1.0000x reference)
#include <cuda_runtime.h>
#include <cuda_bf16.h>

// Problem constants
#define BATCH 2
#define SEQ   2048
#define DIM   1024
#define NH    16
#define HD    64
#define MROWS (BATCH*SEQ)          // 4096
#define QKV_N (3*DIM)              // 3072

// Scratch (device globals; no allocation allowed)
__device__ float g_q[BATCH*NH*SEQ*HD];   // [b][h][s][d], pre-scaled by 1/sqrt(HD)
__device__ float g_k[BATCH*NH*SEQ*HD];
__device__ float g_v[BATCH*NH*SEQ*HD];
__device__ float g_ao[BATCH*SEQ*DIM];    // attention output, [b][s][h*64+d]

// ---------------------------------------------------------------------------
// SGEMM 128x128x8, 256 threads, 8x8 micro-tile.
// ---------------------------------------------------------------------------
#define BM 128
#define BN 128
#define BK 8
#define TM 8
#define TN 8

__global__ __launch_bounds__(256) void sgemm_qkv(const float* __restrict__ A,
                                                 const float* __restrict__ B,
                                                 const float* __restrict__ bias) {
    __shared__ float As[BK][BM];
    __shared__ float Bs[BK][BN];
    const int M = MROWS, N = QKV_N, K = DIM;
    const int bx = blockIdx.x, by = blockIdx.y;
    const int tid = threadIdx.x;

    const int arow = tid >> 1;            // 0..127
    const int acol = (tid & 1) * 4;       // 0 or 4
    const int brow = tid >> 5;            // 0..7
    const int bcol = (tid & 31) * 4;      // 0..124

    const float* Ag = A + (size_t)(by * BM) * K;
    const float* Bg = B + bx * BN;

    float acc[TM][TN];
    #pragma unroll
    for (int i = 0; i < TM; i++)
        #pragma unroll
        for (int j = 0; j < TN; j++) acc[i][j] = 0.f;

    const int trow = (tid >> 4) * TM;
    const int tcol = (tid & 15) * TN;

    for (int k0 = 0; k0 < K; k0 += BK) {
        float4 a4 = *(const float4*)(Ag + (size_t)arow * K + k0 + acol);
        As[acol + 0][arow] = a4.x;
        As[acol + 1][arow] = a4.y;
        As[acol + 2][arow] = a4.z;
        As[acol + 3][arow] = a4.w;
        float4 b4 = *(const float4*)(Bg + (size_t)(k0 + brow) * N + bcol);
        *(float4*)&Bs[brow][bcol] = b4;
        __syncthreads();
        #pragma unroll
        for (int kk = 0; kk < BK; kk++) {
            float af[TM], bf[TN];
            #pragma unroll
            for (int i = 0; i < TM; i++) af[i] = As[kk][trow + i];
            #pragma unroll
            for (int j = 0; j < TN; j++) bf[j] = Bs[kk][tcol + j];
            #pragma unroll
            for (int i = 0; i < TM; i++)
                #pragma unroll
                for (int j = 0; j < TN; j++) acc[i][j] += af[i] * bf[j];
        }
        __syncthreads();
    }

    // Scatter epilogue: qkv[r][c] -> g_q/g_k/g_v [b][h][s][d]; scale folded into Q.
    #pragma unroll
    for (int i = 0; i < TM; i++) {
        int r  = by * BM + trow + i;
        int b_ = r >> 11;
        int s  = r & (SEQ - 1);
        #pragma unroll
        for (int j = 0; j < TN; j++) {
            int c = bx * BN + tcol + j;
            float val = acc[i][j] + bias[c];
            int part = c >> 10;
            int h = (c >> 6) & (NH - 1);
            int d = c & (HD - 1);
            int idx = (((b_ * NH + h) * SEQ) + s) * HD + d;
            if (part == 0)      g_q[idx] = val * 0.125f;   // 1/sqrt(64)
            else if (part == 1) g_k[idx] = val;
            else                g_v[idx] = val;
        }
    }
}

__global__ __launch_bounds__(256) void sgemm_out(const float* __restrict__ B,
                                                 const float* __restrict__ bias,
                                                 float* __restrict__ C) {
    __shared__ float As[BK][BM];
    __shared__ float Bs[BK][BN];
    const int N = DIM, K = DIM;
    const int bx = blockIdx.x, by = blockIdx.y;
    const int tid = threadIdx.x;

    const int arow = tid >> 1;
    const int acol = (tid & 1) * 4;
    const int brow = tid >> 5;
    const int bcol = (tid & 31) * 4;

    const float* Ag = g_ao + (size_t)(by * BM) * K;
    const float* Bg = B + bx * BN;

    float acc[TM][TN];
    #pragma unroll
    for (int i = 0; i < TM; i++)
        #pragma unroll
        for (int j = 0; j < TN; j++) acc[i][j] = 0.f;

    const int trow = (tid >> 4) * TM;
    const int tcol = (tid & 15) * TN;

    for (int k0 = 0; k0 < K; k0 += BK) {
        float4 a4 = *(const float4*)(Ag + (size_t)arow * K + k0 + acol);
        As[acol + 0][arow] = a4.x;
        As[acol + 1][arow] = a4.y;
        As[acol + 2][arow] = a4.z;
        As[acol + 3][arow] = a4.w;
        float4 b4 = *(const float4*)(Bg + (size_t)(k0 + brow) * N + bcol);
        *(float4*)&Bs[brow][bcol] = b4;
        __syncthreads();
        #pragma unroll
        for (int kk = 0; kk < BK; kk++) {
            float af[TM], bf[TN];
            #pragma unroll
            for (int i = 0; i < TM; i++) af[i] = As[kk][trow + i];
            #pragma unroll
            for (int j = 0; j < TN; j++) bf[j] = Bs[kk][tcol + j];
            #pragma unroll
            for (int i = 0; i < TM; i++)
                #pragma unroll
                for (int j = 0; j < TN; j++) acc[i][j] += af[i] * bf[j];
        }
        __syncthreads();
    }

    #pragma unroll
    for (int i = 0; i < TM; i++) {
        int r = by * BM + trow + i;
        #pragma unroll
        for (int j = 0; j < TN; j += 4) {
            int c = bx * BN + tcol + j;
            float4 o;
            o.x = acc[i][j + 0] + bias[c + 0];
            o.y = acc[i][j + 1] + bias[c + 1];
            o.z = acc[i][j + 2] + bias[c + 2];
            o.w = acc[i][j + 3] + bias[c + 3];
            *(float4*)(C + (size_t)r * N + c) = o;
        }
    }
}

// ---------------------------------------------------------------------------
// Causal flash attention. Q tile 64, K tile 32, Hd=64. 256 threads (16x16).
// grid = (32 q-tiles, 32 b*h)
// ---------------------------------------------------------------------------
#define AQ 64
#define AK 32

__global__ __launch_bounds__(256) void attn_kernel() {
    __shared__ float Qts[HD][AQ + 4];   // [d][row], pad 4 -> 16B aligned float4 reads
    __shared__ float Kts[HD][AK + 1];   // [d][j]
    __shared__ float Vs[AK][HD];        // [j][d]
    __shared__ float Ps[AQ][AK + 1];    // [row][j]
    __shared__ float m_s[AQ], l_s[AQ], corr_s[AQ];

    const int qt = blockIdx.x;          // 0..31
    const int bh = blockIdx.y;          // 0..31
    const size_t base = (size_t)bh * SEQ * HD;
    const float* Qp = g_q + base;
    const float* Kp = g_k + base;
    const float* Vp = g_v + base;

    const int tid = threadIdx.x;
    const int ty = tid >> 4, tx = tid & 15;

    // Load Q tile transposed: Qts[d][row]
    for (int i = tid; i < AQ * (HD / 4); i += 256) {
        int r = i >> 4, c4 = (i & 15) * 4;
        float4 q4 = *(const float4*)(Qp + (size_t)(qt * AQ + r) * HD + c4);
        Qts[c4 + 0][r] = q4.x;
        Qts[c4 + 1][r] = q4.y;
        Qts[c4 + 2][r] = q4.z;
        Qts[c4 + 3][r] = q4.w;
    }
    if (tid < AQ) { m_s[tid] = -1e30f; l_s[tid] = 0.f; }

    float acc[4][4];
    #pragma unroll
    for (int a = 0; a < 4; a++)
        #pragma unroll
        for (int b = 0; b < 4; b++) acc[a][b] = 0.f;

    __syncthreads();

    const int ntiles = 2 * qt + 2;
    for (int jt = 0; jt < ntiles; jt++) {
        // Load K tile transposed + V tile
        for (int i = tid; i < AK * (HD / 4); i += 256) {
            int j = i >> 4, c4 = (i & 15) * 4;
            float4 k4 = *(const float4*)(Kp + (size_t)(jt * AK + j) * HD + c4);
            Kts[c4 + 0][j] = k4.x;
            Kts[c4 + 1][j] = k4.y;
            Kts[c4 + 2][j] = k4.z;
            Kts[c4 + 3][j] = k4.w;
            float4 v4 = *(const float4*)(Vp + (size_t)(jt * AK + j) * HD + c4);
            *(float4*)&Vs[j][c4] = v4;
        }
        __syncthreads();

        // S = Q K^T  (each thread: 4 rows x 2 cols)
        float s[4][2] = {{0.f, 0.f}, {0.f, 0.f}, {0.f, 0.f}, {0.f, 0.f}};
        #pragma unroll
        for (int d = 0; d < HD; d++) {
            float4 qf = *(const float4*)&Qts[d][ty * 4];
            float k0 = Kts[d][tx * 2];
            float k1 = Kts[d][tx * 2 + 1];
            s[0][0] += qf.x * k0; s[0][1] += qf.x * k1;
            s[1][0] += qf.y * k0; s[1][1] += qf.y * k1;
            s[2][0] += qf.z * k0; s[2][1] += qf.z * k1;
            s[3][0] += qf.w * k0; s[3][1] += qf.w * k1;
        }
        // Causal mask; write raw scores to Ps
        #pragma unroll
        for (int a = 0; a < 4; a++) {
            int qi = qt * AQ + ty * 4 + a;
            #pragma unroll
            for (int b = 0; b < 2; b++) {
                int kj = jt * AK + tx * 2 + b;
                Ps[ty * 4 + a][tx * 2 + b] = (kj <= qi) ? s[a][b] : -1e30f;
            }
        }
        __syncthreads();

        // Online softmax: 8 warps x 8 rows, 32 lanes over 32 cols
        {
            int wid = tid >> 5, lane = tid & 31;
            #pragma unroll
            for (int rr = 0; rr < 8; rr++) {
                int row = wid * 8 + rr;
                float v = Ps[row][lane];
                float mx = v;
                #pragma unroll
                for (int o = 16; o > 0; o >>= 1)
                    mx = fmaxf(mx, __shfl_xor_sync(0xffffffffu, mx, o));
                float mold = m_s[row];
                float mnew = fmaxf(mold, mx);
                float p = __expf(v - mnew);
                float psum = p;
                #pragma unroll
                for (int o = 16; o > 0; o >>= 1)
                    psum += __shfl_xor_sync(0xffffffffu, psum, o);
                Ps[row][lane] = p;
                if (lane == 0) {
                    float corr = __expf(mold - mnew);
                    corr_s[row] = corr;
                    l_s[row] = l_s[row] * corr + psum;
                    m_s[row] = mnew;
                }
            }
        }
        __syncthreads();

        // O = O*corr + P V  (each thread: 4 rows x 4 d-cols)
        #pragma unroll
        for (int a = 0; a < 4; a++) {
            float c = corr_s[ty * 4 + a];
            #pragma unroll
            for (int b = 0; b < 4; b++) acc[a][b] *= c;
        }
        #pragma unroll
        for (int j = 0; j < AK; j++) {
            float4 vf = *(const float4*)&Vs[j][tx * 4];
            float pf0 = Ps[ty * 4 + 0][j];
            float pf1 = Ps[ty * 4 + 1][j];
            float pf2 = Ps[ty * 4 + 2][j];
            float pf3 = Ps[ty * 4 + 3][j];
            acc[0][0] += pf0 * vf.x; acc[0][1] += pf0 * vf.y; acc[0][2] += pf0 * vf.z; acc[0][3] += pf0 * vf.w;
            acc[1][0] += pf1 * vf.x; acc[1][1] += pf1 * vf.y; acc[1][2] += pf1 * vf.z; acc[1][3] += pf1 * vf.w;
            acc[2][0] += pf2 * vf.x; acc[2][1] += pf2 * vf.y; acc[2][2] += pf2 * vf.z; acc[2][3] += pf2 * vf.w;
            acc[3][0] += pf3 * vf.x; acc[3][1] += pf3 * vf.y; acc[3][2] += pf3 * vf.z; acc[3][3] += pf3 * vf.w;
        }
        __syncthreads();
    }

    // Write out: g_ao[b][s][h*64+d]
    int b_ = bh >> 4, h = bh & (NH - 1);
    #pragma unroll
    for (int a = 0; a < 4; a++) {
        int row = ty * 4 + a;
        float inv = 1.f / l_s[row];
        int sidx = qt * AQ + row;
        float* dst = g_ao + ((size_t)b_ * SEQ + sidx) * DIM + h * HD + tx * 4;
        float4 o;
        o.x = acc[a][0] * inv;
        o.y = acc[a][1] * inv;
        o.z = acc[a][2] * inv;
        o.w = acc[a][3] * inv;
        *(float4*)dst = o;
    }
}

// ---------------------------------------------------------------------------
extern "C" void kernel_launch(void* const* d_in, const int* in_sizes, int n_in,
                              void* d_out, int out_size) {
    const float* x     = (const float*)d_in[0];
    const float* W_qkv = (const float*)d_in[1];
    const float* b_qkv = (const float*)d_in[2];
    const float* W_out = (const float*)d_in[3];
    const float* b_out = (const float*)d_in[4];
    float* out = (float*)d_out;

    sgemm_qkv<<<dim3(QKV_N / BN, MROWS / BM), 256>>>(x, W_qkv, b_qkv);
    attn_kernel<<<dim3(SEQ / AQ, BATCH * NH), 256>>>();
    sgemm_out<<<dim3(DIM / BN, MROWS / BM), 256>>>(W_out, b_out, out);
}

// round 2
// speedup vs baseline: 1.6718x; 1.6718x over previous
#include <cuda_runtime.h>
#include <cuda_bf16.h>
#include <cstdint>

// Problem constants
#define BATCH 2
#define SEQ   2048
#define DIM   1024
#define NH    16
#define HD    64
#define MROWS (BATCH*SEQ)          // 4096
#define QKV_N (3*DIM)              // 3072

// Scratch (device globals; no allocation allowed)
__device__ float g_q[BATCH*NH*SEQ*HD];   // [b][h][s][d], pre-scaled by 1/sqrt(HD)
__device__ float g_k[BATCH*NH*SEQ*HD];
__device__ float g_v[BATCH*NH*SEQ*HD];
__device__ float g_ao[BATCH*SEQ*DIM];    // attention output, [b][s][h*64+d]

// ---------------------------------------------------------------------------
// tf32 tensor-core GEMM: CTA tile 128x128x32, 8 warps (2m x 4n), warp 64x32.
// A fragments via ldmatrix.x4.b16 from row-major As (stride 36 floats = 144B).
// B fragments via scalar LDS from k-major Bs (stride 136 floats, 8 mod 32).
// ---------------------------------------------------------------------------
#define GBM 128
#define GBN 128
#define GBK 32
#define AS_STRIDE 36    // floats per As row (144 B)
#define BS_STRIDE 136   // floats per Bs k-row

__device__ __forceinline__ uint32_t f2tf(float x) {
    uint32_t y;
    asm("cvt.rna.tf32.f32 %0, %1;" : "=r"(y) : "f"(x));
    return y;
}

__device__ __forceinline__ void mma_tf32(float (&d)[4],
                                         const uint32_t (&a)[4],
                                         const uint32_t (&b)[2]) {
    asm volatile(
        "mma.sync.aligned.m16n8k8.row.col.f32.tf32.tf32.f32 "
        "{%0,%1,%2,%3}, {%4,%5,%6,%7}, {%8,%9}, {%0,%1,%2,%3};"
        : "+f"(d[0]), "+f"(d[1]), "+f"(d[2]), "+f"(d[3])
        : "r"(a[0]), "r"(a[1]), "r"(a[2]), "r"(a[3]), "r"(b[0]), "r"(b[1]));
}

// Computes acc[mt][nt][4] for CTA tile (blockIdx.y * 128 rows, blockIdx.x * 128 cols).
// A: [M, K] row-major fp32 (K = DIM). B: [K, N] row-major fp32.
__device__ __forceinline__ void gemm_tile_tf32(const float* __restrict__ A,
                                               const float* __restrict__ B,
                                               const int N,
                                               float (&acc)[4][4][4]) {
    __shared__ __align__(16) float As[GBM * AS_STRIDE];
    __shared__ __align__(16) float Bs[GBK * BS_STRIDE];

    const int K = DIM;
    const int tid = threadIdx.x;
    const int lane = tid & 31;
    const int w = tid >> 5;
    const int warpM = (w & 1) * 64;
    const int warpN = (w >> 1) * 32;
    const int g = lane >> 2;   // 0..7
    const int t = lane & 3;    // 0..3

    const float* Ag = A + (size_t)(blockIdx.y * GBM) * K;
    const float* Bg = B + blockIdx.x * GBN;

    // ldmatrix per-lane offset (bytes): lanes 0-7 -> (rows+0, cols 0-3),
    // 8-15 -> (rows+8, cols 0-3), 16-23 -> (rows+0, cols 4-7), 24-31 -> (rows+8, cols 4-7)
    const int sub = lane >> 3, r8 = lane & 7;
    const uint32_t lofA = (uint32_t)((((sub & 1) * 8 + r8) * AS_STRIDE) * 4 + (sub >> 1) * 16);
    const uint32_t as_base = (uint32_t)__cvta_generic_to_shared(As);

    // global->smem staging coords
    const int a_row = tid >> 3;        // 0..31 (+ it*32)
    const int a_k4  = (tid & 7) * 4;   // k offset
    const int b_k   = tid >> 5;        // 0..7  (+ it*8)
    const int b_n4  = (tid & 31) * 4;  // n offset

    float4 pa[4], pb[4];
    #pragma unroll
    for (int it = 0; it < 4; it++) {
        pa[it] = *(const float4*)(Ag + (size_t)(a_row + it * 32) * K + a_k4);
        pb[it] = *(const float4*)(Bg + (size_t)(b_k + it * 8) * N + b_n4);
    }

    const int NKT = K / GBK;   // 32
    for (int kt = 0; kt < NKT; kt++) {
        // store staged tile with tf32 RNA conversion
        #pragma unroll
        for (int it = 0; it < 4; it++) {
            float4 v = pa[it], c;
            c.x = __uint_as_float(f2tf(v.x));
            c.y = __uint_as_float(f2tf(v.y));
            c.z = __uint_as_float(f2tf(v.z));
            c.w = __uint_as_float(f2tf(v.w));
            *(float4*)&As[(a_row + it * 32) * AS_STRIDE + a_k4] = c;
            float4 u = pb[it], d;
            d.x = __uint_as_float(f2tf(u.x));
            d.y = __uint_as_float(f2tf(u.y));
            d.z = __uint_as_float(f2tf(u.z));
            d.w = __uint_as_float(f2tf(u.w));
            *(float4*)&Bs[(b_k + it * 8) * BS_STRIDE + b_n4] = d;
        }
        __syncthreads();

        if (kt + 1 < NKT) {
            const float* Ag2 = Ag + (kt + 1) * GBK;
            const float* Bg2 = Bg + (size_t)(kt + 1) * GBK * N;
            #pragma unroll
            for (int it = 0; it < 4; it++) {
                pa[it] = *(const float4*)(Ag2 + (size_t)(a_row + it * 32) * K + a_k4);
                pb[it] = *(const float4*)(Bg2 + (size_t)(b_k + it * 8) * N + b_n4);
            }
        }

        #pragma unroll
        for (int ks = 0; ks < 4; ks++) {
            uint32_t af[4][4];
            #pragma unroll
            for (int mt = 0; mt < 4; mt++) {
                uint32_t addr = as_base
                              + (uint32_t)(((warpM + mt * 16) * AS_STRIDE) * 4 + ks * 32)
                              + lofA;
                asm volatile(
                    "ldmatrix.sync.aligned.m8n8.x4.shared.b16 {%0,%1,%2,%3}, [%4];"
                    : "=r"(af[mt][0]), "=r"(af[mt][1]), "=r"(af[mt][2]), "=r"(af[mt][3])
                    : "r"(addr));
            }
            uint32_t bf[4][2];
            #pragma unroll
            for (int nt = 0; nt < 4; nt++) {
                int n = warpN + nt * 8 + g;
                bf[nt][0] = __float_as_uint(Bs[(ks * 8 + t) * BS_STRIDE + n]);
                bf[nt][1] = __float_as_uint(Bs[(ks * 8 + t + 4) * BS_STRIDE + n]);
            }
            #pragma unroll
            for (int mt = 0; mt < 4; mt++)
                #pragma unroll
                for (int nt = 0; nt < 4; nt++)
                    mma_tf32(acc[mt][nt], af[mt], bf[nt]);
        }
        __syncthreads();
    }
}

// QKV projection: C = x @ W_qkv + b_qkv, scattered into g_q/g_k/g_v per head.
__global__ __launch_bounds__(256) void gemm_qkv_tc(const float* __restrict__ A,
                                                   const float* __restrict__ B,
                                                   const float* __restrict__ bias) {
    float acc[4][4][4];
    #pragma unroll
    for (int i = 0; i < 4; i++)
        #pragma unroll
        for (int j = 0; j < 4; j++)
            #pragma unroll
            for (int k = 0; k < 4; k++) acc[i][j][k] = 0.f;

    gemm_tile_tf32(A, B, QKV_N, acc);

    const int tid = threadIdx.x;
    const int lane = tid & 31;
    const int w = tid >> 5;
    const int warpM = (w & 1) * 64;
    const int warpN = (w >> 1) * 32;
    const int g = lane >> 2, t = lane & 3;

    #pragma unroll
    for (int mt = 0; mt < 4; mt++) {
        #pragma unroll
        for (int nt = 0; nt < 4; nt++) {
            int col = blockIdx.x * GBN + warpN + nt * 8 + t * 2;
            float b0 = bias[col], b1 = bias[col + 1];
            int part = col >> 10;
            int h = (col >> 6) & (NH - 1);
            int d = col & (HD - 1);
            #pragma unroll
            for (int half = 0; half < 2; half++) {
                int r = blockIdx.y * GBM + warpM + mt * 16 + g + half * 8;
                int b_ = r >> 11, s = r & (SEQ - 1);
                int idx = (((b_ * NH + h) * SEQ) + s) * HD + d;
                float v0 = acc[mt][nt][half * 2 + 0] + b0;
                float v1 = acc[mt][nt][half * 2 + 1] + b1;
                if (part == 0) {
                    g_q[idx] = v0 * 0.125f;      // fold 1/sqrt(64)
                    g_q[idx + 1] = v1 * 0.125f;
                } else if (part == 1) {
                    g_k[idx] = v0; g_k[idx + 1] = v1;
                } else {
                    g_v[idx] = v0; g_v[idx + 1] = v1;
                }
            }
        }
    }
}

// Output projection: out = g_ao @ W_out + b_out
__global__ __launch_bounds__(256) void gemm_out_tc(const float* __restrict__ B,
                                                   const float* __restrict__ bias,
                                                   float* __restrict__ C) {
    float acc[4][4][4];
    #pragma unroll
    for (int i = 0; i < 4; i++)
        #pragma unroll
        for (int j = 0; j < 4; j++)
            #pragma unroll
            for (int k = 0; k < 4; k++) acc[i][j][k] = 0.f;

    gemm_tile_tf32(g_ao, B, DIM, acc);

    const int tid = threadIdx.x;
    const int lane = tid & 31;
    const int w = tid >> 5;
    const int warpM = (w & 1) * 64;
    const int warpN = (w >> 1) * 32;
    const int g = lane >> 2, t = lane & 3;

    #pragma unroll
    for (int mt = 0; mt < 4; mt++) {
        #pragma unroll
        for (int nt = 0; nt < 4; nt++) {
            int col = blockIdx.x * GBN + warpN + nt * 8 + t * 2;
            float b0 = bias[col], b1 = bias[col + 1];
            #pragma unroll
            for (int half = 0; half < 2; half++) {
                int r = blockIdx.y * GBM + warpM + mt * 16 + g + half * 8;
                float2 o;
                o.x = acc[mt][nt][half * 2 + 0] + b0;
                o.y = acc[mt][nt][half * 2 + 1] + b1;
                *(float2*)(C + (size_t)r * DIM + col) = o;
            }
        }
    }
}

// ---------------------------------------------------------------------------
// Causal flash attention. Q tile 64, K tile 32, Hd=64. 256 threads (16x16).
// grid = (32 q-tiles, 32 b*h); longest blocks scheduled first.
// ---------------------------------------------------------------------------
#define AQ 64
#define AK 32

__global__ __launch_bounds__(256) void attn_kernel() {
    __shared__ float Qts[HD][AQ + 4];
    __shared__ float Kts[HD][AK + 1];
    __shared__ float Vs[AK][HD];
    __shared__ float Ps[AQ][AK + 1];
    __shared__ float m_s[AQ], l_s[AQ], corr_s[AQ];

    const int qt = (gridDim.x - 1) - blockIdx.x;   // longest first
    const int bh = blockIdx.y;
    const size_t base = (size_t)bh * SEQ * HD;
    const float* Qp = g_q + base;
    const float* Kp = g_k + base;
    const float* Vp = g_v + base;

    const int tid = threadIdx.x;
    const int ty = tid >> 4, tx = tid & 15;

    for (int i = tid; i < AQ * (HD / 4); i += 256) {
        int r = i >> 4, c4 = (i & 15) * 4;
        float4 q4 = *(const float4*)(Qp + (size_t)(qt * AQ + r) * HD + c4);
        Qts[c4 + 0][r] = q4.x;
        Qts[c4 + 1][r] = q4.y;
        Qts[c4 + 2][r] = q4.z;
        Qts[c4 + 3][r] = q4.w;
    }
    if (tid < AQ) { m_s[tid] = -1e30f; l_s[tid] = 0.f; }

    float acc[4][4];
    #pragma unroll
    for (int a = 0; a < 4; a++)
        #pragma unroll
        for (int b = 0; b < 4; b++) acc[a][b] = 0.f;

    __syncthreads();

    const int ntiles = 2 * qt + 2;
    for (int jt = 0; jt < ntiles; jt++) {
        for (int i = tid; i < AK * (HD / 4); i += 256) {
            int j = i >> 4, c4 = (i & 15) * 4;
            float4 k4 = *(const float4*)(Kp + (size_t)(jt * AK + j) * HD + c4);
            Kts[c4 + 0][j] = k4.x;
            Kts[c4 + 1][j] = k4.y;
            Kts[c4 + 2][j] = k4.z;
            Kts[c4 + 3][j] = k4.w;
            float4 v4 = *(const float4*)(Vp + (size_t)(jt * AK + j) * HD + c4);
            *(float4*)&Vs[j][c4] = v4;
        }
        __syncthreads();

        float s[4][2] = {{0.f, 0.f}, {0.f, 0.f}, {0.f, 0.f}, {0.f, 0.f}};
        #pragma unroll
        for (int d = 0; d < HD; d++) {
            float4 qf = *(const float4*)&Qts[d][ty * 4];
            float k0 = Kts[d][tx * 2];
            float k1 = Kts[d][tx * 2 + 1];
            s[0][0] += qf.x * k0; s[0][1] += qf.x * k1;
            s[1][0] += qf.y * k0; s[1][1] += qf.y * k1;
            s[2][0] += qf.z * k0; s[2][1] += qf.z * k1;
            s[3][0] += qf.w * k0; s[3][1] += qf.w * k1;
        }
        #pragma unroll
        for (int a = 0; a < 4; a++) {
            int qi = qt * AQ + ty * 4 + a;
            #pragma unroll
            for (int b = 0; b < 2; b++) {
                int kj = jt * AK + tx * 2 + b;
                Ps[ty * 4 + a][tx * 2 + b] = (kj <= qi) ? s[a][b] : -1e30f;
            }
        }
        __syncthreads();

        {
            int wid = tid >> 5, lane = tid & 31;
            #pragma unroll
            for (int rr = 0; rr < 8; rr++) {
                int row = wid * 8 + rr;
                float v = Ps[row][lane];
                float mx = v;
                #pragma unroll
                for (int o = 16; o > 0; o >>= 1)
                    mx = fmaxf(mx, __shfl_xor_sync(0xffffffffu, mx, o));
                float mold = m_s[row];
                float mnew = fmaxf(mold, mx);
                float p = __expf(v - mnew);
                float psum = p;
                #pragma unroll
                for (int o = 16; o > 0; o >>= 1)
                    psum += __shfl_xor_sync(0xffffffffu, psum, o);
                Ps[row][lane] = p;
                if (lane == 0) {
                    float corr = __expf(mold - mnew);
                    corr_s[row] = corr;
                    l_s[row] = l_s[row] * corr + psum;
                    m_s[row] = mnew;
                }
            }
        }
        __syncthreads();

        #pragma unroll
        for (int a = 0; a < 4; a++) {
            float c = corr_s[ty * 4 + a];
            #pragma unroll
            for (int b = 0; b < 4; b++) acc[a][b] *= c;
        }
        #pragma unroll
        for (int j = 0; j < AK; j++) {
            float4 vf = *(const float4*)&Vs[j][tx * 4];
            float pf0 = Ps[ty * 4 + 0][j];
            float pf1 = Ps[ty * 4 + 1][j];
            float pf2 = Ps[ty * 4 + 2][j];
            float pf3 = Ps[ty * 4 + 3][j];
            acc[0][0] += pf0 * vf.x; acc[0][1] += pf0 * vf.y; acc[0][2] += pf0 * vf.z; acc[0][3] += pf0 * vf.w;
            acc[1][0] += pf1 * vf.x; acc[1][1] += pf1 * vf.y; acc[1][2] += pf1 * vf.z; acc[1][3] += pf1 * vf.w;
            acc[2][0] += pf2 * vf.x; acc[2][1] += pf2 * vf.y; acc[2][2] += pf2 * vf.z; acc[2][3] += pf2 * vf.w;
            acc[3][0] += pf3 * vf.x; acc[3][1] += pf3 * vf.y; acc[3][2] += pf3 * vf.z; acc[3][3] += pf3 * vf.w;
        }
        __syncthreads();
    }

    int b_ = bh >> 4, h = bh & (NH - 1);
    #pragma unroll
    for (int a = 0; a < 4; a++) {
        int row = ty * 4 + a;
        float inv = 1.f / l_s[row];
        int sidx = qt * AQ + row;
        float* dst = g_ao + ((size_t)b_ * SEQ + sidx) * DIM + h * HD + tx * 4;
        float4 o;
        o.x = acc[a][0] * inv;
        o.y = acc[a][1] * inv;
        o.z = acc[a][2] * inv;
        o.w = acc[a][3] * inv;
        *(float4*)dst = o;
    }
}

// ---------------------------------------------------------------------------
extern "C" void kernel_launch(void* const* d_in, const int* in_sizes, int n_in,
                              void* d_out, int out_size) {
    const float* x     = (const float*)d_in[0];
    const float* W_qkv = (const float*)d_in[1];
    const float* b_qkv = (const float*)d_in[2];
    const float* W_out = (const float*)d_in[3];
    const float* b_out = (const float*)d_in[4];
    float* out = (float*)d_out;

    gemm_qkv_tc<<<dim3(QKV_N / GBN, MROWS / GBM), 256>>>(x, W_qkv, b_qkv);
    attn_kernel<<<dim3(SEQ / AQ, BATCH * NH), 256>>>();
    gemm_out_tc<<<dim3(DIM / GBN, MROWS / GBM), 256>>>(W_out, b_out, out);
}

// round 3
// speedup vs baseline: 3.7761x; 2.2586x over previous
#include <cuda_runtime.h>
#include <cuda_bf16.h>
#include <cstdint>

// Problem constants
#define BATCH 2
#define SEQ   2048
#define DIM   1024
#define NH    16
#define HD    64
#define MROWS (BATCH*SEQ)          // 4096
#define QKV_N (3*DIM)              // 3072

// Scratch (device globals; no allocation allowed)
__device__ float g_q[BATCH*NH*SEQ*HD];   // [b][h][s][d], pre-scaled by 1/sqrt(HD)
__device__ float g_k[BATCH*NH*SEQ*HD];
__device__ float g_v[BATCH*NH*SEQ*HD];
__device__ float g_ao[BATCH*SEQ*DIM];    // attention output, [b][s][h*64+d]

__device__ __forceinline__ uint32_t f2tf(float x) {
    uint32_t y;
    asm("cvt.rna.tf32.f32 %0, %1;" : "=r"(y) : "f"(x));
    return y;
}

__device__ __forceinline__ void mma_tf32(float (&d)[4],
                                         const uint32_t (&a)[4],
                                         const uint32_t (&b)[2]) {
    asm volatile(
        "mma.sync.aligned.m16n8k8.row.col.f32.tf32.tf32.f32 "
        "{%0,%1,%2,%3}, {%4,%5,%6,%7}, {%8,%9}, {%0,%1,%2,%3};"
        : "+f"(d[0]), "+f"(d[1]), "+f"(d[2]), "+f"(d[3])
        : "r"(a[0]), "r"(a[1]), "r"(a[2]), "r"(a[3]), "r"(b[0]), "r"(b[1]));
}

// ---------------------------------------------------------------------------
// tf32 tensor-core GEMM: CTA tile 128x128x32, 8 warps (2m x 4n), warp 64x32.
// ---------------------------------------------------------------------------
#define GBM 128
#define GBN 128
#define GBK 32
#define AS_STRIDE 36
#define BS_STRIDE 136

__device__ __forceinline__ void gemm_tile_tf32(const float* __restrict__ A,
                                               const float* __restrict__ B,
                                               const int N,
                                               float (&acc)[4][4][4]) {
    __shared__ __align__(16) float As[GBM * AS_STRIDE];
    __shared__ __align__(16) float Bs[GBK * BS_STRIDE];

    const int K = DIM;
    const int tid = threadIdx.x;
    const int lane = tid & 31;
    const int w = tid >> 5;
    const int warpM = (w & 1) * 64;
    const int warpN = (w >> 1) * 32;
    const int g = lane >> 2;
    const int t = lane & 3;

    const float* Ag = A + (size_t)(blockIdx.y * GBM) * K;
    const float* Bg = B + blockIdx.x * GBN;

    const int sub = lane >> 3, r8 = lane & 7;
    const uint32_t lofA = (uint32_t)((((sub & 1) * 8 + r8) * AS_STRIDE) * 4 + (sub >> 1) * 16);
    const uint32_t as_base = (uint32_t)__cvta_generic_to_shared(As);

    const int a_row = tid >> 3;
    const int a_k4  = (tid & 7) * 4;
    const int b_k   = tid >> 5;
    const int b_n4  = (tid & 31) * 4;

    float4 pa[4], pb[4];
    #pragma unroll
    for (int it = 0; it < 4; it++) {
        pa[it] = *(const float4*)(Ag + (size_t)(a_row + it * 32) * K + a_k4);
        pb[it] = *(const float4*)(Bg + (size_t)(b_k + it * 8) * N + b_n4);
    }

    const int NKT = K / GBK;
    for (int kt = 0; kt < NKT; kt++) {
        #pragma unroll
        for (int it = 0; it < 4; it++) {
            float4 v = pa[it], c;
            c.x = __uint_as_float(f2tf(v.x));
            c.y = __uint_as_float(f2tf(v.y));
            c.z = __uint_as_float(f2tf(v.z));
            c.w = __uint_as_float(f2tf(v.w));
            *(float4*)&As[(a_row + it * 32) * AS_STRIDE + a_k4] = c;
            float4 u = pb[it], d;
            d.x = __uint_as_float(f2tf(u.x));
            d.y = __uint_as_float(f2tf(u.y));
            d.z = __uint_as_float(f2tf(u.z));
            d.w = __uint_as_float(f2tf(u.w));
            *(float4*)&Bs[(b_k + it * 8) * BS_STRIDE + b_n4] = d;
        }
        __syncthreads();

        if (kt + 1 < NKT) {
            const float* Ag2 = Ag + (kt + 1) * GBK;
            const float* Bg2 = Bg + (size_t)(kt + 1) * GBK * N;
            #pragma unroll
            for (int it = 0; it < 4; it++) {
                pa[it] = *(const float4*)(Ag2 + (size_t)(a_row + it * 32) * K + a_k4);
                pb[it] = *(const float4*)(Bg2 + (size_t)(b_k + it * 8) * N + b_n4);
            }
        }

        #pragma unroll
        for (int ks = 0; ks < 4; ks++) {
            uint32_t af[4][4];
            #pragma unroll
            for (int mt = 0; mt < 4; mt++) {
                uint32_t addr = as_base
                              + (uint32_t)(((warpM + mt * 16) * AS_STRIDE) * 4 + ks * 32)
                              + lofA;
                asm volatile(
                    "ldmatrix.sync.aligned.m8n8.x4.shared.b16 {%0,%1,%2,%3}, [%4];"
                    : "=r"(af[mt][0]), "=r"(af[mt][1]), "=r"(af[mt][2]), "=r"(af[mt][3])
                    : "r"(addr));
            }
            uint32_t bf[4][2];
            #pragma unroll
            for (int nt = 0; nt < 4; nt++) {
                int n = warpN + nt * 8 + g;
                bf[nt][0] = __float_as_uint(Bs[(ks * 8 + t) * BS_STRIDE + n]);
                bf[nt][1] = __float_as_uint(Bs[(ks * 8 + t + 4) * BS_STRIDE + n]);
            }
            #pragma unroll
            for (int mt = 0; mt < 4; mt++)
                #pragma unroll
                for (int nt = 0; nt < 4; nt++)
                    mma_tf32(acc[mt][nt], af[mt], bf[nt]);
        }
        __syncthreads();
    }
}

__global__ __launch_bounds__(256) void gemm_qkv_tc(const float* __restrict__ A,
                                                   const float* __restrict__ B,
                                                   const float* __restrict__ bias) {
    float acc[4][4][4];
    #pragma unroll
    for (int i = 0; i < 4; i++)
        #pragma unroll
        for (int j = 0; j < 4; j++)
            #pragma unroll
            for (int k = 0; k < 4; k++) acc[i][j][k] = 0.f;

    gemm_tile_tf32(A, B, QKV_N, acc);

    const int tid = threadIdx.x;
    const int lane = tid & 31;
    const int w = tid >> 5;
    const int warpM = (w & 1) * 64;
    const int warpN = (w >> 1) * 32;
    const int g = lane >> 2, t = lane & 3;

    #pragma unroll
    for (int mt = 0; mt < 4; mt++) {
        #pragma unroll
        for (int nt = 0; nt < 4; nt++) {
            int col = blockIdx.x * GBN + warpN + nt * 8 + t * 2;
            float b0 = bias[col], b1 = bias[col + 1];
            int part = col >> 10;
            int h = (col >> 6) & (NH - 1);
            int d = col & (HD - 1);
            #pragma unroll
            for (int half = 0; half < 2; half++) {
                int r = blockIdx.y * GBM + warpM + mt * 16 + g + half * 8;
                int b_ = r >> 11, s = r & (SEQ - 1);
                int idx = (((b_ * NH + h) * SEQ) + s) * HD + d;
                float v0 = acc[mt][nt][half * 2 + 0] + b0;
                float v1 = acc[mt][nt][half * 2 + 1] + b1;
                if (part == 0) {
                    g_q[idx] = v0 * 0.125f;
                    g_q[idx + 1] = v1 * 0.125f;
                } else if (part == 1) {
                    g_k[idx] = v0; g_k[idx + 1] = v1;
                } else {
                    g_v[idx] = v0; g_v[idx + 1] = v1;
                }
            }
        }
    }
}

__global__ __launch_bounds__(256) void gemm_out_tc(const float* __restrict__ B,
                                                   const float* __restrict__ bias,
                                                   float* __restrict__ C) {
    float acc[4][4][4];
    #pragma unroll
    for (int i = 0; i < 4; i++)
        #pragma unroll
        for (int j = 0; j < 4; j++)
            #pragma unroll
            for (int k = 0; k < 4; k++) acc[i][j][k] = 0.f;

    gemm_tile_tf32(g_ao, B, DIM, acc);

    const int tid = threadIdx.x;
    const int lane = tid & 31;
    const int w = tid >> 5;
    const int warpM = (w & 1) * 64;
    const int warpN = (w >> 1) * 32;
    const int g = lane >> 2, t = lane & 3;

    #pragma unroll
    for (int mt = 0; mt < 4; mt++) {
        #pragma unroll
        for (int nt = 0; nt < 4; nt++) {
            int col = blockIdx.x * GBN + warpN + nt * 8 + t * 2;
            float b0 = bias[col], b1 = bias[col + 1];
            #pragma unroll
            for (int half = 0; half < 2; half++) {
                int r = blockIdx.y * GBM + warpM + mt * 16 + g + half * 8;
                float2 o;
                o.x = acc[mt][nt][half * 2 + 0] + b0;
                o.y = acc[mt][nt][half * 2 + 1] + b1;
                *(float2*)(C + (size_t)r * DIM + col) = o;
            }
        }
    }
}

// ---------------------------------------------------------------------------
// Tensor-core causal flash attention (tf32 mma).
// CTA: 128 q-rows x 64 kv per tile, 8 warps x 16 q-rows, Hd=64.
// grid = (16 q-tiles, 32 b*h); longest q-tiles scheduled first.
// ---------------------------------------------------------------------------
#define ATQ 128
#define ATK 64
#define QS_STRIDE 68   // (17 odd x 16B rows) -> conflict-free ldmatrix
#define KS_STRIDE 68   // S B-frags: (4g+t) mod 32 distinct
#define VS_STRIDE 72   // PV B-frags: (8t+g) mod 32 distinct
#define PS_STRIDE 68
#define ATTN_SMEM ((ATQ*QS_STRIDE + ATK*KS_STRIDE + ATK*VS_STRIDE + ATQ*PS_STRIDE) * 4)

__global__ __launch_bounds__(256) void attn_tc() {
    extern __shared__ float sm[];
    float* Qs = sm;                          // [128][68]
    float* Ks = Qs + ATQ * QS_STRIDE;        // [64][68]
    float* Vs = Ks + ATK * KS_STRIDE;        // [64][72]
    float* Ps = Vs + ATK * VS_STRIDE;        // [128][68]

    const int tid = threadIdx.x;
    const int lane = tid & 31;
    const int w = tid >> 5;
    const int g = lane >> 2, t = lane & 3;

    const int qt = (gridDim.x - 1) - blockIdx.x;   // longest first
    const int bh = blockIdx.y;
    const int q0 = qt * ATQ;
    const size_t base = (size_t)bh * SEQ * HD;
    const float* Qp = g_q + base;
    const float* Kp = g_k + base;
    const float* Vp = g_v + base;

    const int sub = lane >> 3, r8 = lane & 7;
    const int lrow = (sub & 1) * 8 + r8;
    const int lcol16 = (sub >> 1) * 16;  // bytes
    const uint32_t qs_base = (uint32_t)__cvta_generic_to_shared(Qs);
    const uint32_t ps_base = (uint32_t)__cvta_generic_to_shared(Ps);

    // Load Q tile (tf32-converted) into Qs
    for (int i = tid; i < ATQ * (HD / 4); i += 256) {
        int r = i >> 4, c4 = (i & 15) * 4;
        float4 v = *(const float4*)(Qp + (size_t)(q0 + r) * HD + c4);
        float4 c;
        c.x = __uint_as_float(f2tf(v.x));
        c.y = __uint_as_float(f2tf(v.y));
        c.z = __uint_as_float(f2tf(v.z));
        c.w = __uint_as_float(f2tf(v.w));
        *(float4*)&Qs[r * QS_STRIDE + c4] = c;
    }

    float o[8][4];
    #pragma unroll
    for (int nt = 0; nt < 8; nt++)
        #pragma unroll
        for (int c = 0; c < 4; c++) o[nt][c] = 0.f;
    float m0 = -1e30f, m1 = -1e30f, l0 = 0.f, l1 = 0.f;

    const int ntiles = 2 * qt + 2;
    for (int jt = 0; jt < ntiles; jt++) {
        if (jt) __syncthreads();
        const int kv0 = jt * ATK;
        // Load K,V tiles (tf32-converted)
        for (int i = tid; i < ATK * (HD / 4); i += 256) {
            int r = i >> 4, c4 = (i & 15) * 4;
            float4 kk = *(const float4*)(Kp + (size_t)(kv0 + r) * HD + c4);
            float4 vv = *(const float4*)(Vp + (size_t)(kv0 + r) * HD + c4);
            float4 ck, cv;
            ck.x = __uint_as_float(f2tf(kk.x));
            ck.y = __uint_as_float(f2tf(kk.y));
            ck.z = __uint_as_float(f2tf(kk.z));
            ck.w = __uint_as_float(f2tf(kk.w));
            cv.x = __uint_as_float(f2tf(vv.x));
            cv.y = __uint_as_float(f2tf(vv.y));
            cv.z = __uint_as_float(f2tf(vv.z));
            cv.w = __uint_as_float(f2tf(vv.w));
            *(float4*)&Ks[r * KS_STRIDE + c4] = ck;
            *(float4*)&Vs[r * VS_STRIDE + c4] = cv;
        }
        __syncthreads();

        // S = Q K^T : per warp 16x64
        float s[8][4];
        #pragma unroll
        for (int nt = 0; nt < 8; nt++)
            #pragma unroll
            for (int c = 0; c < 4; c++) s[nt][c] = 0.f;

        #pragma unroll
        for (int ks = 0; ks < 8; ks++) {
            uint32_t a[4];
            uint32_t addr = qs_base
                          + (uint32_t)(((w * 16 + lrow) * QS_STRIDE) * 4 + ks * 32)
                          + (uint32_t)lcol16;
            asm volatile(
                "ldmatrix.sync.aligned.m8n8.x4.shared.b16 {%0,%1,%2,%3}, [%4];"
                : "=r"(a[0]), "=r"(a[1]), "=r"(a[2]), "=r"(a[3]) : "r"(addr));
            #pragma unroll
            for (int nt = 0; nt < 8; nt++) {
                uint32_t b[2];
                const float* kp = &Ks[(nt * 8 + g) * KS_STRIDE + ks * 8 + t];
                b[0] = __float_as_uint(kp[0]);
                b[1] = __float_as_uint(kp[4]);
                mma_tf32(s[nt], a, b);
            }
        }

        // Causal mask (only the two diagonal tiles)
        if (jt >= 2 * qt) {
            int r0 = q0 + w * 16 + g, r1 = r0 + 8;
            #pragma unroll
            for (int nt = 0; nt < 8; nt++) {
                int c0 = kv0 + nt * 8 + 2 * t;
                if (c0 > r0)     s[nt][0] = -1e30f;
                if (c0 + 1 > r0) s[nt][1] = -1e30f;
                if (c0 > r1)     s[nt][2] = -1e30f;
                if (c0 + 1 > r1) s[nt][3] = -1e30f;
            }
        }

        // Online softmax (rows g and g+8; row stats shared across quad)
        float mx0 = -1e30f, mx1 = -1e30f;
        #pragma unroll
        for (int nt = 0; nt < 8; nt++) {
            mx0 = fmaxf(mx0, fmaxf(s[nt][0], s[nt][1]));
            mx1 = fmaxf(mx1, fmaxf(s[nt][2], s[nt][3]));
        }
        mx0 = fmaxf(mx0, __shfl_xor_sync(0xffffffffu, mx0, 1));
        mx0 = fmaxf(mx0, __shfl_xor_sync(0xffffffffu, mx0, 2));
        mx1 = fmaxf(mx1, __shfl_xor_sync(0xffffffffu, mx1, 1));
        mx1 = fmaxf(mx1, __shfl_xor_sync(0xffffffffu, mx1, 2));
        float mn0 = fmaxf(m0, mx0), mn1 = fmaxf(m1, mx1);
        float corr0 = __expf(m0 - mn0), corr1 = __expf(m1 - mn1);
        m0 = mn0; m1 = mn1;
        float sum0 = 0.f, sum1 = 0.f;
        #pragma unroll
        for (int nt = 0; nt < 8; nt++) {
            s[nt][0] = __expf(s[nt][0] - mn0);
            s[nt][1] = __expf(s[nt][1] - mn0);
            s[nt][2] = __expf(s[nt][2] - mn1);
            s[nt][3] = __expf(s[nt][3] - mn1);
            sum0 += s[nt][0] + s[nt][1];
            sum1 += s[nt][2] + s[nt][3];
        }
        l0 = l0 * corr0 + sum0;
        l1 = l1 * corr1 + sum1;
        #pragma unroll
        for (int nt = 0; nt < 8; nt++) {
            o[nt][0] *= corr0; o[nt][1] *= corr0;
            o[nt][2] *= corr1; o[nt][3] *= corr1;
        }

        // Stage P (tf32) for ldmatrix A-frags (warp-private rows)
        {
            int pr0 = (w * 16 + g) * PS_STRIDE;
            int pr1 = pr0 + 8 * PS_STRIDE;
            #pragma unroll
            for (int nt = 0; nt < 8; nt++) {
                int cc = nt * 8 + 2 * t;
                Ps[pr0 + cc]     = __uint_as_float(f2tf(s[nt][0]));
                Ps[pr0 + cc + 1] = __uint_as_float(f2tf(s[nt][1]));
                Ps[pr1 + cc]     = __uint_as_float(f2tf(s[nt][2]));
                Ps[pr1 + cc + 1] = __uint_as_float(f2tf(s[nt][3]));
            }
        }
        __syncwarp();

        // O += P V
        #pragma unroll
        for (int ks = 0; ks < 8; ks++) {
            uint32_t a[4];
            uint32_t addr = ps_base
                          + (uint32_t)(((w * 16 + lrow) * PS_STRIDE) * 4 + ks * 32)
                          + (uint32_t)lcol16;
            asm volatile(
                "ldmatrix.sync.aligned.m8n8.x4.shared.b16 {%0,%1,%2,%3}, [%4];"
                : "=r"(a[0]), "=r"(a[1]), "=r"(a[2]), "=r"(a[3]) : "r"(addr));
            #pragma unroll
            for (int nt = 0; nt < 8; nt++) {
                uint32_t b[2];
                const float* vp = &Vs[(ks * 8 + t) * VS_STRIDE + nt * 8 + g];
                b[0] = __float_as_uint(vp[0]);
                b[1] = __float_as_uint(vp[4 * VS_STRIDE]);
                mma_tf32(o[nt], a, b);
            }
        }
    }

    // Final l reduction across quad, normalize, write to g_ao
    l0 += __shfl_xor_sync(0xffffffffu, l0, 1);
    l0 += __shfl_xor_sync(0xffffffffu, l0, 2);
    l1 += __shfl_xor_sync(0xffffffffu, l1, 1);
    l1 += __shfl_xor_sync(0xffffffffu, l1, 2);
    float inv0 = 1.f / l0, inv1 = 1.f / l1;

    int b_ = bh >> 4, h = bh & (NH - 1);
    int r0 = q0 + w * 16 + g, r1 = r0 + 8;
    float* dst0 = g_ao + ((size_t)b_ * SEQ + r0) * DIM + h * HD;
    float* dst1 = g_ao + ((size_t)b_ * SEQ + r1) * DIM + h * HD;
    #pragma unroll
    for (int nt = 0; nt < 8; nt++) {
        int cc = nt * 8 + 2 * t;
        float2 o0, o1;
        o0.x = o[nt][0] * inv0; o0.y = o[nt][1] * inv0;
        o1.x = o[nt][2] * inv1; o1.y = o[nt][3] * inv1;
        *(float2*)(dst0 + cc) = o0;
        *(float2*)(dst1 + cc) = o1;
    }
}

// ---------------------------------------------------------------------------
extern "C" void kernel_launch(void* const* d_in, const int* in_sizes, int n_in,
                              void* d_out, int out_size) {
    const float* x     = (const float*)d_in[0];
    const float* W_qkv = (const float*)d_in[1];
    const float* b_qkv = (const float*)d_in[2];
    const float* W_out = (const float*)d_in[3];
    const float* b_out = (const float*)d_in[4];
    float* out = (float*)d_out;

    cudaFuncSetAttribute(attn_tc, cudaFuncAttributeMaxDynamicSharedMemorySize, ATTN_SMEM);

    gemm_qkv_tc<<<dim3(QKV_N / GBN, MROWS / GBM), 256>>>(x, W_qkv, b_qkv);
    attn_tc<<<dim3(SEQ / ATQ, BATCH * NH), 256, ATTN_SMEM>>>();
    gemm_out_tc<<<dim3(DIM / GBN, MROWS / GBM), 256>>>(W_out, b_out, out);
}

// round 4
// speedup vs baseline: 4.0006x; 1.0595x over previous
#include <cuda_runtime.h>
#include <cuda_bf16.h>
#include <cstdint>

// Problem constants
#define BATCH 2
#define SEQ   2048
#define DIM   1024
#define NH    16
#define HD    64
#define MROWS (BATCH*SEQ)          // 4096
#define QKV_N (3*DIM)              // 3072

// Scratch (device globals; no allocation allowed)
__device__ float g_q[BATCH*NH*SEQ*HD];   // [b][h][s][d], pre-scaled by 1/sqrt(HD)
__device__ float g_k[BATCH*NH*SEQ*HD];   // [b][h][s][d]
__device__ float g_vt[BATCH*NH*HD*SEQ];  // [b][h][d][s]  (transposed V)
__device__ float g_ao[BATCH*SEQ*DIM];    // attention output, [b][s][h*64+d]

__device__ __forceinline__ uint32_t f2tf(float x) {
    uint32_t y;
    asm("cvt.rna.tf32.f32 %0, %1;" : "=r"(y) : "f"(x));
    return y;
}

__device__ __forceinline__ void mma_tf32(float (&d)[4],
                                         const uint32_t (&a)[4],
                                         const uint32_t (&b)[2]) {
    asm volatile(
        "mma.sync.aligned.m16n8k8.row.col.f32.tf32.tf32.f32 "
        "{%0,%1,%2,%3}, {%4,%5,%6,%7}, {%8,%9}, {%0,%1,%2,%3};"
        : "+f"(d[0]), "+f"(d[1]), "+f"(d[2]), "+f"(d[3])
        : "r"(a[0]), "r"(a[1]), "r"(a[2]), "r"(a[3]), "r"(b[0]), "r"(b[1]));
}

// ---------------------------------------------------------------------------
// tf32 tensor-core GEMM: CTA tile 128x128x32, 8 warps (2m x 4n), warp 64x32.
// ---------------------------------------------------------------------------
#define GBM 128
#define GBN 128
#define GBK 32
#define AS_STRIDE 36
#define BS_STRIDE 136

__device__ __forceinline__ void gemm_tile_tf32(const float* __restrict__ A,
                                               const float* __restrict__ B,
                                               const int N,
                                               float (&acc)[4][4][4]) {
    __shared__ __align__(16) float As[GBM * AS_STRIDE];
    __shared__ __align__(16) float Bs[GBK * BS_STRIDE];

    const int K = DIM;
    const int tid = threadIdx.x;
    const int lane = tid & 31;
    const int w = tid >> 5;
    const int warpM = (w & 1) * 64;
    const int warpN = (w >> 1) * 32;
    const int g = lane >> 2;
    const int t = lane & 3;

    const float* Ag = A + (size_t)(blockIdx.y * GBM) * K;
    const float* Bg = B + blockIdx.x * GBN;

    const int sub = lane >> 3, r8 = lane & 7;
    const uint32_t lofA = (uint32_t)((((sub & 1) * 8 + r8) * AS_STRIDE) * 4 + (sub >> 1) * 16);
    const uint32_t as_base = (uint32_t)__cvta_generic_to_shared(As);

    const int a_row = tid >> 3;
    const int a_k4  = (tid & 7) * 4;
    const int b_k   = tid >> 5;
    const int b_n4  = (tid & 31) * 4;

    float4 pa[4], pb[4];
    #pragma unroll
    for (int it = 0; it < 4; it++) {
        pa[it] = *(const float4*)(Ag + (size_t)(a_row + it * 32) * K + a_k4);
        pb[it] = *(const float4*)(Bg + (size_t)(b_k + it * 8) * N + b_n4);
    }

    const int NKT = K / GBK;
    for (int kt = 0; kt < NKT; kt++) {
        #pragma unroll
        for (int it = 0; it < 4; it++) {
            float4 v = pa[it], c;
            c.x = __uint_as_float(f2tf(v.x));
            c.y = __uint_as_float(f2tf(v.y));
            c.z = __uint_as_float(f2tf(v.z));
            c.w = __uint_as_float(f2tf(v.w));
            *(float4*)&As[(a_row + it * 32) * AS_STRIDE + a_k4] = c;
            float4 u = pb[it], d;
            d.x = __uint_as_float(f2tf(u.x));
            d.y = __uint_as_float(f2tf(u.y));
            d.z = __uint_as_float(f2tf(u.z));
            d.w = __uint_as_float(f2tf(u.w));
            *(float4*)&Bs[(b_k + it * 8) * BS_STRIDE + b_n4] = d;
        }
        __syncthreads();

        if (kt + 1 < NKT) {
            const float* Ag2 = Ag + (kt + 1) * GBK;
            const float* Bg2 = Bg + (size_t)(kt + 1) * GBK * N;
            #pragma unroll
            for (int it = 0; it < 4; it++) {
                pa[it] = *(const float4*)(Ag2 + (size_t)(a_row + it * 32) * K + a_k4);
                pb[it] = *(const float4*)(Bg2 + (size_t)(b_k + it * 8) * N + b_n4);
            }
        }

        #pragma unroll
        for (int ks = 0; ks < 4; ks++) {
            uint32_t af[4][4];
            #pragma unroll
            for (int mt = 0; mt < 4; mt++) {
                uint32_t addr = as_base
                              + (uint32_t)(((warpM + mt * 16) * AS_STRIDE) * 4 + ks * 32)
                              + lofA;
                asm volatile(
                    "ldmatrix.sync.aligned.m8n8.x4.shared.b16 {%0,%1,%2,%3}, [%4];"
                    : "=r"(af[mt][0]), "=r"(af[mt][1]), "=r"(af[mt][2]), "=r"(af[mt][3])
                    : "r"(addr));
            }
            uint32_t bf[4][2];
            #pragma unroll
            for (int nt = 0; nt < 4; nt++) {
                int n = warpN + nt * 8 + g;
                bf[nt][0] = __float_as_uint(Bs[(ks * 8 + t) * BS_STRIDE + n]);
                bf[nt][1] = __float_as_uint(Bs[(ks * 8 + t + 4) * BS_STRIDE + n]);
            }
            #pragma unroll
            for (int mt = 0; mt < 4; mt++)
                #pragma unroll
                for (int nt = 0; nt < 4; nt++)
                    mma_tf32(acc[mt][nt], af[mt], bf[nt]);
        }
        __syncthreads();
    }
}

__global__ __launch_bounds__(256) void gemm_qkv_tc(const float* __restrict__ A,
                                                   const float* __restrict__ B,
                                                   const float* __restrict__ bias) {
    float acc[4][4][4];
    #pragma unroll
    for (int i = 0; i < 4; i++)
        #pragma unroll
        for (int j = 0; j < 4; j++)
            #pragma unroll
            for (int k = 0; k < 4; k++) acc[i][j][k] = 0.f;

    gemm_tile_tf32(A, B, QKV_N, acc);

    const int tid = threadIdx.x;
    const int lane = tid & 31;
    const int w = tid >> 5;
    const int warpM = (w & 1) * 64;
    const int warpN = (w >> 1) * 32;
    const int g = lane >> 2, t = lane & 3;

    #pragma unroll
    for (int mt = 0; mt < 4; mt++) {
        #pragma unroll
        for (int nt = 0; nt < 4; nt++) {
            int col = blockIdx.x * GBN + warpN + nt * 8 + t * 2;
            float b0 = bias[col], b1 = bias[col + 1];
            int part = col >> 10;
            int h = (col >> 6) & (NH - 1);
            int d = col & (HD - 1);
            #pragma unroll
            for (int half = 0; half < 2; half++) {
                int r = blockIdx.y * GBM + warpM + mt * 16 + g + half * 8;
                int b_ = r >> 11, s = r & (SEQ - 1);
                float v0 = acc[mt][nt][half * 2 + 0] + b0;
                float v1 = acc[mt][nt][half * 2 + 1] + b1;
                if (part == 0) {
                    int idx = (((b_ * NH + h) * SEQ) + s) * HD + d;
                    g_q[idx] = v0 * 0.125f;
                    g_q[idx + 1] = v1 * 0.125f;
                } else if (part == 1) {
                    int idx = (((b_ * NH + h) * SEQ) + s) * HD + d;
                    g_k[idx] = v0; g_k[idx + 1] = v1;
                } else {
                    size_t vb = ((size_t)(b_ * NH + h) * HD + d) * SEQ + s;
                    g_vt[vb] = v0;
                    g_vt[vb + SEQ] = v1;
                }
            }
        }
    }
}

__global__ __launch_bounds__(256) void gemm_out_tc(const float* __restrict__ B,
                                                   const float* __restrict__ bias,
                                                   float* __restrict__ C) {
    float acc[4][4][4];
    #pragma unroll
    for (int i = 0; i < 4; i++)
        #pragma unroll
        for (int j = 0; j < 4; j++)
            #pragma unroll
            for (int k = 0; k < 4; k++) acc[i][j][k] = 0.f;

    gemm_tile_tf32(g_ao, B, DIM, acc);

    const int tid = threadIdx.x;
    const int lane = tid & 31;
    const int w = tid >> 5;
    const int warpM = (w & 1) * 64;
    const int warpN = (w >> 1) * 32;
    const int g = lane >> 2, t = lane & 3;

    #pragma unroll
    for (int mt = 0; mt < 4; mt++) {
        #pragma unroll
        for (int nt = 0; nt < 4; nt++) {
            int col = blockIdx.x * GBN + warpN + nt * 8 + t * 2;
            float b0 = bias[col], b1 = bias[col + 1];
            #pragma unroll
            for (int half = 0; half < 2; half++) {
                int r = blockIdx.y * GBM + warpM + mt * 16 + g + half * 8;
                float2 o;
                o.x = acc[mt][nt][half * 2 + 0] + b0;
                o.y = acc[mt][nt][half * 2 + 1] + b1;
                *(float2*)(C + (size_t)r * DIM + col) = o;
            }
        }
    }
}

// ---------------------------------------------------------------------------
// Tensor-core causal flash attention (tf32 mma), all fragments via ldmatrix.
// CTA: 128 q-rows x 64 kv per tile, 8 warps x 16 q-rows, Hd=64.
// PV A-fragments redistributed from S-accumulators via quad shfl (no Ps smem).
// grid = (16 q-tiles, 32 b*h); longest q-tiles scheduled first.
// ---------------------------------------------------------------------------
#define ATQ 128
#define ATK 64
#define QS_S 68   // stride 68: 8-row ldmatrix phase covers all 32 banks
#define KS_S 68
#define VT_S 68
#define ATTN_SMEM ((ATQ*QS_S + ATK*KS_S + HD*VT_S) * 4)

__global__ __launch_bounds__(256, 2) void attn_tc() {
    extern __shared__ float sm[];
    float* Qs = sm;                     // [128][68]  (q, d)
    float* Ks = Qs + ATQ * QS_S;        // [64][68]   (kv, d)  n-major for QK^T
    float* Vt = Ks + ATK * KS_S;        // [64][68]   (d, kv)  n-major for PV

    const int tid = threadIdx.x;
    const int lane = tid & 31;
    const int wp = tid >> 5;
    const int g = lane >> 2, t = lane & 3;

    const int qt = (gridDim.x - 1) - blockIdx.x;   // longest first
    const int bh = blockIdx.y;
    const int q0 = qt * ATQ;
    const float* Qp  = g_q  + (size_t)bh * SEQ * HD;
    const float* Kp  = g_k  + (size_t)bh * SEQ * HD;
    const float* Vtp = g_vt + (size_t)bh * HD * SEQ;

    const int sub = lane >> 3, r8 = lane & 7;
    // A-frag lane offset (tiles: row+0/+8 x col+0/+16B)
    const uint32_t lofQ = (uint32_t)((((sub & 1) * 8 + r8) * QS_S) * 4 + (sub >> 1) * 16);
    // B-frag lane layout (tiles: chunk+0/+16B x row+0/+8)
    const int brow = (sub >> 1) * 8 + r8;
    const int bchunk = (sub & 1) * 16;
    const uint32_t qs_base = (uint32_t)__cvta_generic_to_shared(Qs);
    const uint32_t ks_base = (uint32_t)__cvta_generic_to_shared(Ks);
    const uint32_t vt_base = (uint32_t)__cvta_generic_to_shared(Vt);

    // Load Q tile (tf32-converted)
    for (int i = tid; i < ATQ * (HD / 4); i += 256) {
        int r = i >> 4, c4 = (i & 15) * 4;
        float4 v = *(const float4*)(Qp + (size_t)(q0 + r) * HD + c4);
        float4 c;
        c.x = __uint_as_float(f2tf(v.x));
        c.y = __uint_as_float(f2tf(v.y));
        c.z = __uint_as_float(f2tf(v.z));
        c.w = __uint_as_float(f2tf(v.w));
        *(float4*)&Qs[r * QS_S + c4] = c;
    }

    float o[8][4];
    #pragma unroll
    for (int nt = 0; nt < 8; nt++)
        #pragma unroll
        for (int c = 0; c < 4; c++) o[nt][c] = 0.f;
    float m0 = -1e30f, m1 = -1e30f, l0 = 0.f, l1 = 0.f;

    const int srcA = (lane & ~3) | (t >> 1);
    const int srcB = srcA + 2;

    const int ntiles = 2 * qt + 2;
    for (int jt = 0; jt < ntiles; jt++) {
        if (jt) __syncthreads();
        const int kv0 = jt * ATK;
        // Stage K (kv-major) and V^T (d-major), tf32-converted
        for (int i = tid; i < ATK * (HD / 4); i += 256) {
            int r = i >> 4, c4 = (i & 15) * 4;
            float4 kk = *(const float4*)(Kp + (size_t)(kv0 + r) * HD + c4);
            float4 ck;
            ck.x = __uint_as_float(f2tf(kk.x));
            ck.y = __uint_as_float(f2tf(kk.y));
            ck.z = __uint_as_float(f2tf(kk.z));
            ck.w = __uint_as_float(f2tf(kk.w));
            *(float4*)&Ks[r * KS_S + c4] = ck;
            // here r = d row, c4 = kv offset for Vt
            float4 vv = *(const float4*)(Vtp + (size_t)r * SEQ + kv0 + c4);
            float4 cv;
            cv.x = __uint_as_float(f2tf(vv.x));
            cv.y = __uint_as_float(f2tf(vv.y));
            cv.z = __uint_as_float(f2tf(vv.z));
            cv.w = __uint_as_float(f2tf(vv.w));
            *(float4*)&Vt[r * VT_S + c4] = cv;
        }
        __syncthreads();

        // ---- S = Q K^T (warp: 16q x 64kv) ----
        float s[8][4];
        #pragma unroll
        for (int nt = 0; nt < 8; nt++)
            #pragma unroll
            for (int c = 0; c < 4; c++) s[nt][c] = 0.f;

        #pragma unroll
        for (int ks = 0; ks < 8; ks++) {
            uint32_t a[4];
            uint32_t addr = qs_base
                          + (uint32_t)(((wp * 16) * QS_S) * 4 + ks * 32) + lofQ;
            asm volatile(
                "ldmatrix.sync.aligned.m8n8.x4.shared.b16 {%0,%1,%2,%3}, [%4];"
                : "=r"(a[0]), "=r"(a[1]), "=r"(a[2]), "=r"(a[3]) : "r"(addr));
            #pragma unroll
            for (int p = 0; p < 4; p++) {
                uint32_t bq[4];
                uint32_t baddr = ks_base
                               + (uint32_t)(((p * 16 + brow) * KS_S) * 4 + ks * 32 + bchunk);
                asm volatile(
                    "ldmatrix.sync.aligned.m8n8.x4.shared.b16 {%0,%1,%2,%3}, [%4];"
                    : "=r"(bq[0]), "=r"(bq[1]), "=r"(bq[2]), "=r"(bq[3]) : "r"(baddr));
                uint32_t b0[2] = {bq[0], bq[1]};
                uint32_t b1[2] = {bq[2], bq[3]};
                mma_tf32(s[2 * p], a, b0);
                mma_tf32(s[2 * p + 1], a, b1);
            }
        }

        // Causal mask (only the two diagonal tiles)
        if (jt >= 2 * qt) {
            int r0 = q0 + wp * 16 + g, r1 = r0 + 8;
            #pragma unroll
            for (int nt = 0; nt < 8; nt++) {
                int c0 = kv0 + nt * 8 + 2 * t;
                if (c0 > r0)     s[nt][0] = -1e30f;
                if (c0 + 1 > r0) s[nt][1] = -1e30f;
                if (c0 > r1)     s[nt][2] = -1e30f;
                if (c0 + 1 > r1) s[nt][3] = -1e30f;
            }
        }

        // ---- Online softmax (rows g, g+8; stats shared across quad) ----
        float mx0 = -1e30f, mx1 = -1e30f;
        #pragma unroll
        for (int nt = 0; nt < 8; nt++) {
            mx0 = fmaxf(mx0, fmaxf(s[nt][0], s[nt][1]));
            mx1 = fmaxf(mx1, fmaxf(s[nt][2], s[nt][3]));
        }
        mx0 = fmaxf(mx0, __shfl_xor_sync(0xffffffffu, mx0, 1));
        mx0 = fmaxf(mx0, __shfl_xor_sync(0xffffffffu, mx0, 2));
        mx1 = fmaxf(mx1, __shfl_xor_sync(0xffffffffu, mx1, 1));
        mx1 = fmaxf(mx1, __shfl_xor_sync(0xffffffffu, mx1, 2));
        float mn0 = fmaxf(m0, mx0), mn1 = fmaxf(m1, mx1);
        float corr0 = __expf(m0 - mn0), corr1 = __expf(m1 - mn1);
        m0 = mn0; m1 = mn1;
        float sum0 = 0.f, sum1 = 0.f;
        #pragma unroll
        for (int nt = 0; nt < 8; nt++) {
            s[nt][0] = __expf(s[nt][0] - mn0);
            s[nt][1] = __expf(s[nt][1] - mn0);
            s[nt][2] = __expf(s[nt][2] - mn1);
            s[nt][3] = __expf(s[nt][3] - mn1);
            sum0 += s[nt][0] + s[nt][1];
            sum1 += s[nt][2] + s[nt][3];
        }
        l0 = l0 * corr0 + sum0;
        l1 = l1 * corr1 + sum1;
        #pragma unroll
        for (int nt = 0; nt < 8; nt++) {
            o[nt][0] *= corr0; o[nt][1] *= corr0;
            o[nt][2] *= corr1; o[nt][3] *= corr1;
        }

        // tf32-convert P in registers
        uint32_t pt[8][4];
        #pragma unroll
        for (int nt = 0; nt < 8; nt++)
            #pragma unroll
            for (int c = 0; c < 4; c++) pt[nt][c] = f2tf(s[nt][c]);

        // ---- O += P V : A-frags via quad shfl, B-frags via ldmatrix on Vt ----
        #pragma unroll
        for (int ks = 0; ks < 8; ks++) {
            uint32_t a[4];
            {
                uint32_t x0 = __shfl_sync(0xffffffffu, pt[ks][0], srcA);
                uint32_t x1 = __shfl_sync(0xffffffffu, pt[ks][1], srcA);
                a[0] = (t & 1) ? x1 : x0;
                uint32_t y0 = __shfl_sync(0xffffffffu, pt[ks][2], srcA);
                uint32_t y1 = __shfl_sync(0xffffffffu, pt[ks][3], srcA);
                a[1] = (t & 1) ? y1 : y0;
                uint32_t z0 = __shfl_sync(0xffffffffu, pt[ks][0], srcB);
                uint32_t z1 = __shfl_sync(0xffffffffu, pt[ks][1], srcB);
                a[2] = (t & 1) ? z1 : z0;
                uint32_t w0 = __shfl_sync(0xffffffffu, pt[ks][2], srcB);
                uint32_t w1 = __shfl_sync(0xffffffffu, pt[ks][3], srcB);
                a[3] = (t & 1) ? w1 : w0;
            }
            #pragma unroll
            for (int p = 0; p < 4; p++) {
                uint32_t bq[4];
                uint32_t baddr = vt_base
                               + (uint32_t)(((p * 16 + brow) * VT_S) * 4 + ks * 32 + bchunk);
                asm volatile(
                    "ldmatrix.sync.aligned.m8n8.x4.shared.b16 {%0,%1,%2,%3}, [%4];"
                    : "=r"(bq[0]), "=r"(bq[1]), "=r"(bq[2]), "=r"(bq[3]) : "r"(baddr));
                uint32_t b0[2] = {bq[0], bq[1]};
                uint32_t b1[2] = {bq[2], bq[3]};
                mma_tf32(o[2 * p], a, b0);
                mma_tf32(o[2 * p + 1], a, b1);
            }
        }
    }

    // Final l reduction across quad, normalize, write to g_ao
    l0 += __shfl_xor_sync(0xffffffffu, l0, 1);
    l0 += __shfl_xor_sync(0xffffffffu, l0, 2);
    l1 += __shfl_xor_sync(0xffffffffu, l1, 1);
    l1 += __shfl_xor_sync(0xffffffffu, l1, 2);
    float inv0 = 1.f / l0, inv1 = 1.f / l1;

    int b_ = bh >> 4, h = bh & (NH - 1);
    int r0 = q0 + wp * 16 + g, r1 = r0 + 8;
    float* dst0 = g_ao + ((size_t)b_ * SEQ + r0) * DIM + h * HD;
    float* dst1 = g_ao + ((size_t)b_ * SEQ + r1) * DIM + h * HD;
    #pragma unroll
    for (int nt = 0; nt < 8; nt++) {
        int cc = nt * 8 + 2 * t;
        float2 o0, o1;
        o0.x = o[nt][0] * inv0; o0.y = o[nt][1] * inv0;
        o1.x = o[nt][2] * inv1; o1.y = o[nt][3] * inv1;
        *(float2*)(dst0 + cc) = o0;
        *(float2*)(dst1 + cc) = o1;
    }
}

// ---------------------------------------------------------------------------
extern "C" void kernel_launch(void* const* d_in, const int* in_sizes, int n_in,
                              void* d_out, int out_size) {
    const float* x     = (const float*)d_in[0];
    const float* W_qkv = (const float*)d_in[1];
    const float* b_qkv = (const float*)d_in[2];
    const float* W_out = (const float*)d_in[3];
    const float* b_out = (const float*)d_in[4];
    float* out = (float*)d_out;

    cudaFuncSetAttribute(attn_tc, cudaFuncAttributeMaxDynamicSharedMemorySize, ATTN_SMEM);

    gemm_qkv_tc<<<dim3(QKV_N / GBN, MROWS / GBM), 256>>>(x, W_qkv, b_qkv);
    attn_tc<<<dim3(SEQ / ATQ, BATCH * NH), 256, ATTN_SMEM>>>();
    gemm_out_tc<<<dim3(DIM / GBN, MROWS / GBM), 256>>>(W_out, b_out, out);
}